// round 13
// baseline (speedup 1.0000x reference)
#include <cuda_runtime.h>
#include <cuda_fp16.h>
#include <math.h>

#define N_TOTAL 16384
#define TPB     1024
#define GRID    148
#define ROWS    8
#define K2      5                          // half2 neg regs/thread
#define NNEG_REG (2 * K2 * TPB)            // 10240 neg capacity
#define EPT     (N_TOTAL / TPB)            // 16
#define PADV    64.0f                      // exactly representable in fp16

__device__ float        g_partial[GRID];
__device__ unsigned int g_arrive = 0;

// ---------------------------------------------------------------------------
// Persistent fused kernel — fp16 fused-relu hinge (1 instr/pair).
//  phase 1: per-block deterministic compaction; spos stores c = 1-p directly
//  phase 2: thread hoists its 10 negs as 5 half2 regs; group loop:
//             m2 = hfma2_relu(n2, 1, c2)   // max(0, n+c), one instruction
//             acc2 = hadd2(acc2, m2)
//           pads (n=-64, c=-64, exact in fp16) give m2 = exactly 0
//  phase 3: last block reduces fp32 partials in double, divides by npos*nneg
// ---------------------------------------------------------------------------
__global__ __launch_bounds__(TPB, 1)
void fused_kernel(const int* __restrict__ yt, const float* __restrict__ yp,
                  float* __restrict__ out) {
    extern __shared__ float sm[];          // sneg[max(10240,nneg)] then spos[]
    __shared__ int    wsum[32];
    __shared__ float  s_red[32];
    __shared__ int    s_amlast;

    const int tid  = threadIdx.x;
    const int lane = tid & 31;
    const int warp = tid >> 5;

    // ---- phase 1a: load 16 contiguous elems/thread, count pos ----
    const int base = tid * EPT;
    int4   tt[EPT / 4];
    float4 vv[EPT / 4];
    int cp = 0;
    #pragma unroll
    for (int k = 0; k < EPT / 4; k++) {
        tt[k] = ((const int4*)yt)[(base >> 2) + k];
        vv[k] = ((const float4*)yp)[(base >> 2) + k];
        cp += (tt[k].x == 1) + (tt[k].y == 1) + (tt[k].z == 1) + (tt[k].w == 1);
    }

    // ---- phase 1b: block exclusive scan ----
    int inc = cp;
    #pragma unroll
    for (int o = 1; o < 32; o <<= 1) {
        int t = __shfl_up_sync(0xffffffffu, inc, o);
        if (lane >= o) inc += t;
    }
    if (lane == 31) wsum[warp] = inc;
    __syncthreads();
    if (warp == 0) {
        int w = wsum[lane];
        #pragma unroll
        for (int o = 1; o < 32; o <<= 1) {
            int t = __shfl_up_sync(0xffffffffu, w, o);
            if (lane >= o) w += t;
        }
        wsum[lane] = w;
    }
    __syncthreads();

    const int excl     = inc - cp + (warp > 0 ? wsum[warp - 1] : 0);
    const int npos     = wsum[31];
    const int nneg     = N_TOTAL - npos;
    const int nneg_reg = (nneg > NNEG_REG) ? nneg : NNEG_REG;
    const int npos_pad = (npos + ROWS - 1) & ~(ROWS - 1);
    float* sneg = sm;
    float* spos = sm + nneg_reg;           // holds c = 1 - p

    // ---- phase 1c: scatter (pos stored as c = 1-p) + finite pads ----
    {
        int po = excl;
        int no = base - excl;
        #pragma unroll
        for (int k = 0; k < EPT / 4; k++) {
            if (tt[k].x == 1) spos[po++] = 1.0f - vv[k].x; else sneg[no++] = vv[k].x;
            if (tt[k].y == 1) spos[po++] = 1.0f - vv[k].y; else sneg[no++] = vv[k].y;
            if (tt[k].z == 1) spos[po++] = 1.0f - vv[k].z; else sneg[no++] = vv[k].z;
            if (tt[k].w == 1) spos[po++] = 1.0f - vv[k].w; else sneg[no++] = vv[k].w;
        }
        for (int j = nneg + tid; j < NNEG_REG; j += TPB) sneg[j] = -PADV;
        for (int i = npos + tid; i < npos_pad; i += TPB) spos[i] = -PADV;
    }
    __syncthreads();

    // ---- phase 2a: hoist this thread's 10 negs as 5 half2 regs ----
    __half2 nr2[K2];
    #pragma unroll
    for (int k = 0; k < K2; k++) {
        const float2 f2 = *reinterpret_cast<const float2*>(
            sneg + 2 * (k * TPB + tid));            // conflict-free LDS.64
        nr2[k] = __floats2half2_rn(f2.x, f2.y);
    }

    // ---- phase 2b: group loop — fused-relu fp16, branchless ----
    const __half2 one2 = __float2half2_rn(1.0f);
    const __half2 z2   = __float2half2_rn(0.0f);
    __half2 acc2[ROWS];
    #pragma unroll
    for (int r = 0; r < ROWS; r++) acc2[r] = z2;

    float accv = 0.f;      // fp32 side-accumulator (overflow fallback only)

    for (int r0 = blockIdx.x * ROWS; r0 < npos_pad; r0 += GRID * ROWS) {
        __half2 c2[ROWS];
        #pragma unroll
        for (int r = 0; r < ROWS; r++)
            c2[r] = __float2half2_rn(spos[r0 + r]);   // c already = 1-p

        #pragma unroll
        for (int k = 0; k < K2; k++) {
            const __half2 n2 = nr2[k];
            #pragma unroll
            for (int r = 0; r < ROWS; r++) {
                const __half2 m2 = __hfma2_relu(n2, one2, c2[r]);  // max(0,n+c)
                acc2[r] = __hadd2(acc2[r], m2);
            }
        }
    }

    // correctness-only fallback: nneg > 10240 (> 15 sigma; never in practice)
    if (nneg > NNEG_REG) {
        for (int r0 = blockIdx.x * ROWS; r0 < npos_pad; r0 += GRID * ROWS) {
            float ch[ROWS];
            #pragma unroll
            for (int r = 0; r < ROWS; r++)
                ch[r] = spos[r0 + r];
            for (int j = NNEG_REG + tid; j < nneg; j += TPB) {
                const float nk = sneg[j];
                #pragma unroll
                for (int r = 0; r < ROWS; r++)
                    accv += fmaxf(ch[r] + nk, 0.0f);
            }
        }
    }

    // ---- flush half2 accumulators to fp32 ----
    #pragma unroll
    for (int r = 0; r < ROWS; r++)
        accv += __low2float(acc2[r]) + __high2float(acc2[r]);

    // ---- block reduction (fixed order) ----
    #pragma unroll
    for (int o = 16; o > 0; o >>= 1)
        accv += __shfl_down_sync(0xffffffffu, accv, o);
    if (lane == 0) s_red[warp] = accv;
    __syncthreads();
    if (warp == 0) {
        float w = s_red[lane];
        #pragma unroll
        for (int o = 16; o > 0; o >>= 1)
            w += __shfl_down_sync(0xffffffffu, w, o);
        if (lane == 0) g_partial[blockIdx.x] = w;
    }

    // ---- phase 3: last block finalizes (double, fixed order) ----
    if (tid == 0) {
        __threadfence();
        unsigned int prev = atomicAdd(&g_arrive, 1u);
        s_amlast = (prev == GRID - 1);
    }
    __syncthreads();
    if (!s_amlast) return;
    __threadfence();

    if (warp == 0) {
        double S = 0.0;
        for (int i = lane; i < GRID; i += 32) S += (double)g_partial[i];
        #pragma unroll
        for (int o = 16; o > 0; o >>= 1)
            S += __shfl_down_sync(0xffffffffu, S, o);
        if (lane == 0) {
            out[0] = (float)(S / ((double)npos * (double)nneg));
            g_arrive = 0u;    // reset for next graph replay
        }
    }
}

extern "C" void kernel_launch(void* const* d_in, const int* in_sizes, int n_in,
                              void* d_out, int out_size) {
    const int*   yt = (const int*)d_in[0];
    const float* yp = (const float*)d_in[1];

    // sneg region max(10240, nneg) + pos region (<= N+ROWS)  -> ~107 KB
    const int smem_bytes = (NNEG_REG + N_TOTAL + ROWS + 8) * sizeof(float);
    cudaFuncSetAttribute(fused_kernel,
                         cudaFuncAttributeMaxDynamicSharedMemorySize, smem_bytes);

    fused_kernel<<<GRID, TPB, smem_bytes>>>(yt, yp, (float*)d_out);
}

// round 14
// speedup vs baseline: 1.0135x; 1.0135x over previous
#include <cuda_runtime.h>
#include <cuda_fp16.h>
#include <math.h>

#define N_TOTAL 16384
#define TPB     1024
#define GRID    148
#define ROWS    8
#define GMAX    7                          // fixed groups/block (hot path)
#define SPOS_CAP (GRID * ROWS * GMAX)      // 8288 rows covered by hot path
#define K2      5                          // half2 neg regs/thread
#define NNEG_REG (2 * K2 * TPB)            // 10240 neg capacity (hot path)
#define EPT     (N_TOTAL / TPB)            // 16
#define PADV    64.0f                      // exactly representable in fp16

__device__ float        g_partial[GRID];
__device__ unsigned int g_arrive = 0;

// ---------------------------------------------------------------------------
// Persistent fused kernel — fp16 fused-relu hinge, straight-line main loop.
//  phase 1: per-block deterministic compaction; spos stores c = 1-p, padded
//           to a FIXED 8288 rows so the hot loop has a compile-time trip count
//  phase 2: 10 negs/thread in half2 regs; 7 fully-unrolled groups, each:
//           2x broadcast LDS.128 -> 8x cvt -> 40x { hfma2_relu ; hadd2 }
//           (pads n=-64 / c=-64 are exact in fp16 -> contribute exactly 0)
//  cold fallbacks (never taken for this data) keep arbitrary inputs correct.
//  phase 3: last block reduces fp32 partials in double, divides by npos*nneg
// ---------------------------------------------------------------------------
__global__ __launch_bounds__(TPB, 1)
void fused_kernel(const int* __restrict__ yt, const float* __restrict__ yp,
                  float* __restrict__ out) {
    extern __shared__ float sm[];
    __shared__ int    wsum[32];
    __shared__ float  s_red[32];
    __shared__ int    s_amlast;

    const int tid  = threadIdx.x;
    const int lane = tid & 31;
    const int warp = tid >> 5;

    // ---- phase 1a: load 16 contiguous elems/thread, count pos ----
    const int base = tid * EPT;
    int4   tt[EPT / 4];
    float4 vv[EPT / 4];
    int cp = 0;
    #pragma unroll
    for (int k = 0; k < EPT / 4; k++) {
        tt[k] = ((const int4*)yt)[(base >> 2) + k];
        vv[k] = ((const float4*)yp)[(base >> 2) + k];
        cp += (tt[k].x == 1) + (tt[k].y == 1) + (tt[k].z == 1) + (tt[k].w == 1);
    }

    // ---- phase 1b: block exclusive scan ----
    int inc = cp;
    #pragma unroll
    for (int o = 1; o < 32; o <<= 1) {
        int t = __shfl_up_sync(0xffffffffu, inc, o);
        if (lane >= o) inc += t;
    }
    if (lane == 31) wsum[warp] = inc;
    __syncthreads();
    if (warp == 0) {
        int w = wsum[lane];
        #pragma unroll
        for (int o = 1; o < 32; o <<= 1) {
            int t = __shfl_up_sync(0xffffffffu, w, o);
            if (lane >= o) w += t;
        }
        wsum[lane] = w;
    }
    __syncthreads();

    const int excl     = inc - cp + (warp > 0 ? wsum[warp - 1] : 0);
    const int npos     = wsum[31];
    const int nneg     = N_TOTAL - npos;
    // sneg region: multiple of 4 floats so spos is float4-aligned
    const int nneg_reg = ((nneg > NNEG_REG ? nneg : NNEG_REG) + 3) & ~3;
    const int npos_pad = (npos + ROWS - 1) & ~(ROWS - 1);
    const int pos_cap  = (npos_pad > SPOS_CAP) ? npos_pad : SPOS_CAP;
    float* sneg = sm;
    float* spos = sm + nneg_reg;           // holds c = 1 - p

    // ---- phase 1c: scatter (pos stored as c = 1-p) + finite pads ----
    {
        int po = excl;
        int no = base - excl;
        #pragma unroll
        for (int k = 0; k < EPT / 4; k++) {
            if (tt[k].x == 1) spos[po++] = 1.0f - vv[k].x; else sneg[no++] = vv[k].x;
            if (tt[k].y == 1) spos[po++] = 1.0f - vv[k].y; else sneg[no++] = vv[k].y;
            if (tt[k].z == 1) spos[po++] = 1.0f - vv[k].z; else sneg[no++] = vv[k].z;
            if (tt[k].w == 1) spos[po++] = 1.0f - vv[k].w; else sneg[no++] = vv[k].w;
        }
        for (int j = nneg + tid; j < NNEG_REG; j += TPB) sneg[j] = -PADV;
        for (int i = npos + tid; i < pos_cap;  i += TPB) spos[i] = -PADV;
    }
    __syncthreads();

    // ---- phase 2a: hoist this thread's 10 negs as 5 half2 regs ----
    __half2 nr2[K2];
    #pragma unroll
    for (int k = 0; k < K2; k++) {
        const float2 f2 = *reinterpret_cast<const float2*>(
            sneg + 2 * (k * TPB + tid));            // conflict-free LDS.64
        nr2[k] = __floats2half2_rn(f2.x, f2.y);
    }

    // ---- phase 2b: hot loop — 7 fully-unrolled branchless groups ----
    const __half2 one2 = __float2half2_rn(1.0f);
    const __half2 z2   = __float2half2_rn(0.0f);
    __half2 acc2[ROWS];
    #pragma unroll
    for (int r = 0; r < ROWS; r++) acc2[r] = z2;

    float accv = 0.f;      // fp32 side-accumulator (cold fallbacks only)

    #pragma unroll
    for (int g = 0; g < GMAX; g++) {
        const int r0 = (blockIdx.x + g * GRID) * ROWS;   // < SPOS_CAP
        const float4 ca = *reinterpret_cast<const float4*>(spos + r0);
        const float4 cb = *reinterpret_cast<const float4*>(spos + r0 + 4);
        __half2 c2[ROWS];
        c2[0] = __float2half2_rn(ca.x);
        c2[1] = __float2half2_rn(ca.y);
        c2[2] = __float2half2_rn(ca.z);
        c2[3] = __float2half2_rn(ca.w);
        c2[4] = __float2half2_rn(cb.x);
        c2[5] = __float2half2_rn(cb.y);
        c2[6] = __float2half2_rn(cb.z);
        c2[7] = __float2half2_rn(cb.w);

        #pragma unroll
        for (int k = 0; k < K2; k++) {
            const __half2 n2 = nr2[k];
            #pragma unroll
            for (int r = 0; r < ROWS; r++) {
                const __half2 m2 = __hfma2_relu(n2, one2, c2[r]);  // max(0,n+c)
                acc2[r] = __hadd2(acc2[r], m2);
            }
        }
    }

    // cold fallback 1: rows beyond SPOS_CAP (npos > 8288; never in practice)
    if (npos_pad > SPOS_CAP) {
        for (int r0 = SPOS_CAP + blockIdx.x * ROWS; r0 < npos_pad;
             r0 += GRID * ROWS) {
            __half2 c2[ROWS];
            #pragma unroll
            for (int r = 0; r < ROWS; r++)
                c2[r] = __float2half2_rn(spos[r0 + r]);
            #pragma unroll
            for (int k = 0; k < K2; k++) {
                const __half2 n2 = nr2[k];
                #pragma unroll
                for (int r = 0; r < ROWS; r++)
                    acc2[r] = __hadd2(acc2[r], __hfma2_relu(n2, one2, c2[r]));
            }
        }
    }

    // cold fallback 2: negs beyond 10240 (> 15 sigma; never in practice)
    if (nneg > NNEG_REG) {
        for (int r0 = blockIdx.x * ROWS; r0 < npos_pad; r0 += GRID * ROWS) {
            float ch[ROWS];
            #pragma unroll
            for (int r = 0; r < ROWS; r++)
                ch[r] = spos[r0 + r];
            for (int j = NNEG_REG + tid; j < nneg; j += TPB) {
                const float nk = sneg[j];
                #pragma unroll
                for (int r = 0; r < ROWS; r++)
                    accv += fmaxf(ch[r] + nk, 0.0f);
            }
        }
    }

    // ---- flush half2 accumulators to fp32 ----
    #pragma unroll
    for (int r = 0; r < ROWS; r++)
        accv += __low2float(acc2[r]) + __high2float(acc2[r]);

    // ---- block reduction (fixed order) ----
    #pragma unroll
    for (int o = 16; o > 0; o >>= 1)
        accv += __shfl_down_sync(0xffffffffu, accv, o);
    if (lane == 0) s_red[warp] = accv;
    __syncthreads();
    if (warp == 0) {
        float w = s_red[lane];
        #pragma unroll
        for (int o = 16; o > 0; o >>= 1)
            w += __shfl_down_sync(0xffffffffu, w, o);
        if (lane == 0) g_partial[blockIdx.x] = w;
    }

    // ---- phase 3: last block finalizes (double, fixed order) ----
    if (tid == 0) {
        __threadfence();
        unsigned int prev = atomicAdd(&g_arrive, 1u);
        s_amlast = (prev == GRID - 1);
    }
    __syncthreads();
    if (!s_amlast) return;
    __threadfence();

    if (warp == 0) {
        double S = 0.0;
        for (int i = lane; i < GRID; i += 32) S += (double)g_partial[i];
        #pragma unroll
        for (int o = 16; o > 0; o >>= 1)
            S += __shfl_down_sync(0xffffffffu, S, o);
        if (lane == 0) {
            out[0] = (float)(S / ((double)npos * (double)nneg));
            g_arrive = 0u;    // reset for next graph replay
        }
    }
}

extern "C" void kernel_launch(void* const* d_in, const int* in_sizes, int n_in,
                              void* d_out, int out_size) {
    const int*   yt = (const int*)d_in[0];
    const float* yp = (const float*)d_in[1];

    // sneg region (<= max(10244, nneg+3)) + spos region (<= max(8288+8, N))
    const int smem_bytes = (NNEG_REG + 4 + N_TOTAL + ROWS + 8) * sizeof(float);
    cudaFuncSetAttribute(fused_kernel,
                         cudaFuncAttributeMaxDynamicSharedMemorySize, smem_bytes);

    fused_kernel<<<GRID, TPB, smem_bytes>>>(yt, yp, (float*)d_out);
}

// round 15
// speedup vs baseline: 1.0870x; 1.0725x over previous
#include <cuda_runtime.h>
#include <cuda_fp16.h>
#include <math.h>

#define N_TOTAL   16384
#define CHUNK     128
#define NCHK      (N_TOTAL / CHUNK)        // 128 K1 blocks
#define K1TPB     256
#define TPB       1024
#define GRID      148
#define ROWS      8
#define GMAX      7                        // fixed hot groups/block
#define POS_HOT   (GRID * ROWS * GMAX)     // 8288 rows in hot path
#define K2N       5                        // half2 neg regs/thread
#define NEG_HOT   (2 * K2N * TPB)          // 10240 neg slots in hot path
#define PADV      64.0f                    // exact in fp16

// global scratch (written by K1, read by K2)
__device__ float        g_posc[N_TOTAL + 8];    // c = 1-p, padded with -64
__device__ __half       g_negh[N_TOTAL];        // negs as half, padded with -64
__device__ int          g_npos;
__device__ float        g_partial[GRID];
__device__ unsigned int g_arrive = 0;

// ---------------------------------------------------------------------------
// K1: deterministic one-pass global compaction (no atomics, no global scan).
// Block b: prefix = #pos in [0, b*128) (recounted locally — parallel-cheap),
// ballot-scan of own 128-elem chunk, scatter. Last block writes pads + npos.
// ---------------------------------------------------------------------------
__global__ __launch_bounds__(K1TPB)
void compact_kernel(const int* __restrict__ yt, const float* __restrict__ yp) {
    __shared__ int s_warp[8];
    __shared__ int s_wscan[4];
    __shared__ int s_prefix;

    const int tid  = threadIdx.x;
    const int lane = tid & 31;
    const int w    = tid >> 5;
    const int cs   = blockIdx.x * CHUNK;

    // prefix count over [0, cs)
    int cnt = 0;
    const int4* yt4 = (const int4*)yt;
    for (int i = tid; i < (cs >> 2); i += K1TPB) {
        const int4 t = yt4[i];
        cnt += (t.x == 1) + (t.y == 1) + (t.z == 1) + (t.w == 1);
    }
    #pragma unroll
    for (int o = 16; o > 0; o >>= 1)
        cnt += __shfl_down_sync(0xffffffffu, cnt, o);
    if (lane == 0) s_warp[w] = cnt;

    // own chunk: threads 0..127 hold one element each
    int   lab = 0;
    float val = 0.f;
    if (tid < CHUNK) { lab = yt[cs + tid]; val = yp[cs + tid]; }
    const int flag = (lab == 1);
    const unsigned bal = __ballot_sync(0xffffffffu, flag);
    const int excl = __popc(bal & ((1u << lane) - 1u));
    if (lane == 0 && w < 4) s_wscan[w] = __popc(bal);
    __syncthreads();

    if (tid == 0) {
        int s = 0;
        #pragma unroll
        for (int i = 0; i < 8; i++) s += s_warp[i];
        s_prefix = s;
    }
    __syncthreads();

    const int P = s_prefix;                   // pos before this chunk
    if (tid < CHUNK) {
        int wbase = 0;
        #pragma unroll
        for (int i = 0; i < 4; i++) if (i < w) wbase += s_wscan[i];
        const int lpos = wbase + excl;        // pos rank within chunk
        if (flag) g_posc[P + lpos] = 1.0f - val;
        else      g_negh[(cs - P) + (tid - lpos)] = __float2half(val);
    }

    // last block: pads (disjoint from all scatter targets) + publish npos
    if (blockIdx.x == NCHK - 1) {
        __syncthreads();
        int cpos = 0;
        #pragma unroll
        for (int i = 0; i < 4; i++) cpos += s_wscan[i];
        const int npos = P + cpos;
        const int nneg = N_TOTAL - npos;
        int pos_end = (npos + ROWS - 1) & ~(ROWS - 1);
        if (pos_end < POS_HOT) pos_end = POS_HOT;
        for (int i = npos + tid; i < pos_end; i += K1TPB) g_posc[i] = -PADV;
        for (int j = nneg + tid; j < NEG_HOT; j += K1TPB)
            g_negh[j] = __float2half(-PADV);
        if (tid == 0) g_npos = npos;
    }
}

// ---------------------------------------------------------------------------
// K2: main hinge kernel. Prologue = 5 LDG (negs). 7 fully-unrolled groups:
//   2x LDG.128 row constants -> 8x cvt -> 40x { hfma2_relu ; hadd2 }.
// Pads contribute exactly 0. Cold fallbacks keep arbitrary inputs correct.
// ---------------------------------------------------------------------------
__global__ __launch_bounds__(TPB, 1)
void main_kernel(float* __restrict__ out) {
    __shared__ float s_red[32];
    __shared__ int   s_amlast;

    const int tid  = threadIdx.x;
    const int lane = tid & 31;
    const int warp = tid >> 5;

    // hoist this thread's 10 negs (pre-converted halves)
    const __half2* negh2 = (const __half2*)g_negh;
    __half2 nr2[K2N];
    #pragma unroll
    for (int k = 0; k < K2N; k++)
        nr2[k] = negh2[k * TPB + tid];

    const __half2 one2 = __float2half2_rn(1.0f);
    const __half2 z2   = __float2half2_rn(0.0f);
    __half2 acc2[ROWS];
    #pragma unroll
    for (int r = 0; r < ROWS; r++) acc2[r] = z2;

    // hot loop: 7 branchless groups, row constants via LDG.128 (L2 broadcast)
    #pragma unroll
    for (int g = 0; g < GMAX; g++) {
        const int r0 = (blockIdx.x + g * GRID) * ROWS;     // < POS_HOT
        const float4 ca = *(const float4*)(g_posc + r0);
        const float4 cb = *(const float4*)(g_posc + r0 + 4);
        __half2 c2[ROWS];
        c2[0] = __float2half2_rn(ca.x);  c2[1] = __float2half2_rn(ca.y);
        c2[2] = __float2half2_rn(ca.z);  c2[3] = __float2half2_rn(ca.w);
        c2[4] = __float2half2_rn(cb.x);  c2[5] = __float2half2_rn(cb.y);
        c2[6] = __float2half2_rn(cb.z);  c2[7] = __float2half2_rn(cb.w);

        #pragma unroll
        for (int k = 0; k < K2N; k++) {
            const __half2 n2 = nr2[k];
            #pragma unroll
            for (int r = 0; r < ROWS; r++)
                acc2[r] = __hadd2(acc2[r], __hfma2_relu(n2, one2, c2[r]));
        }
    }

    const int npos      = g_npos;
    const int nneg      = N_TOTAL - npos;
    const int npos_pad8 = (npos + ROWS - 1) & ~(ROWS - 1);
    float accv = 0.f;

    // cold fallback A: rows beyond POS_HOT (npos > 8288; never in practice)
    if (npos_pad8 > POS_HOT) {
        for (int r0 = (blockIdx.x + GMAX * GRID) * ROWS; r0 < npos_pad8;
             r0 += GRID * ROWS) {
            __half2 c2[ROWS];
            #pragma unroll
            for (int r = 0; r < ROWS; r++)
                c2[r] = __float2half2_rn(g_posc[r0 + r]);
            #pragma unroll
            for (int k = 0; k < K2N; k++) {
                const __half2 n2 = nr2[k];
                #pragma unroll
                for (int r = 0; r < ROWS; r++)
                    acc2[r] = __hadd2(acc2[r], __hfma2_relu(n2, one2, c2[r]));
            }
        }
    }

    // cold fallback B: negs beyond NEG_HOT (> 15 sigma; never in practice)
    if (nneg > NEG_HOT) {
        for (int r0 = blockIdx.x * ROWS; r0 < npos_pad8; r0 += GRID * ROWS) {
            float ch[ROWS];
            #pragma unroll
            for (int r = 0; r < ROWS; r++) ch[r] = g_posc[r0 + r];
            for (int j = NEG_HOT + tid; j < nneg; j += TPB) {
                const float nk = __half2float(g_negh[j]);
                #pragma unroll
                for (int r = 0; r < ROWS; r++)
                    accv += fmaxf(ch[r] + nk, 0.0f);
            }
        }
    }

    // flush fp16 accumulators
    #pragma unroll
    for (int r = 0; r < ROWS; r++)
        accv += __low2float(acc2[r]) + __high2float(acc2[r]);

    // block reduction (fixed order)
    #pragma unroll
    for (int o = 16; o > 0; o >>= 1)
        accv += __shfl_down_sync(0xffffffffu, accv, o);
    if (lane == 0) s_red[warp] = accv;
    __syncthreads();
    if (warp == 0) {
        float v = s_red[lane];
        #pragma unroll
        for (int o = 16; o > 0; o >>= 1)
            v += __shfl_down_sync(0xffffffffu, v, o);
        if (lane == 0) g_partial[blockIdx.x] = v;
    }

    // last block finalizes (double, fixed order)
    if (tid == 0) {
        __threadfence();
        unsigned int prev = atomicAdd(&g_arrive, 1u);
        s_amlast = (prev == GRID - 1);
    }
    __syncthreads();
    if (!s_amlast) return;
    __threadfence();

    if (warp == 0) {
        double S = 0.0;
        for (int i = lane; i < GRID; i += 32) S += (double)g_partial[i];
        #pragma unroll
        for (int o = 16; o > 0; o >>= 1)
            S += __shfl_down_sync(0xffffffffu, S, o);
        if (lane == 0) {
            out[0] = (float)(S / ((double)npos * (double)nneg));
            g_arrive = 0u;    // reset for next graph replay
        }
    }
}

extern "C" void kernel_launch(void* const* d_in, const int* in_sizes, int n_in,
                              void* d_out, int out_size) {
    const int*   yt = (const int*)d_in[0];
    const float* yp = (const float*)d_in[1];

    compact_kernel<<<NCHK, K1TPB>>>(yt, yp);
    main_kernel<<<GRID, TPB>>>((float*)d_out);
}

// round 16
// speedup vs baseline: 1.1215x; 1.0318x over previous
#include <cuda_runtime.h>
#include <cuda_fp16.h>
#include <math.h>

#define N_TOTAL   16384
#define CHUNK     128
#define NCHK      (N_TOTAL / CHUNK)        // 128 K1 blocks
#define K1TPB     256
#define TPB       1024
#define GRID      148
#define ROWS      8
#define GMAX      7                        // fixed hot groups/block
#define POS_HOT   (GRID * ROWS * GMAX)     // 8288 rows in hot path
#define K2N       5                        // max half2 neg regs/thread
#define NEG_HOT   (2 * K2N * TPB)          // 10240 neg slots in hot path
#define NEG_BASE  (2 * 4 * TPB)            // 8192: slices 0..3
#define PADV      64.0f                    // exact in fp16

// global scratch (written by K1, read by K2)
__device__ float        g_posc[N_TOTAL + 8];    // c = 1-p, padded with -64
__device__ __half       g_negh[N_TOTAL];        // negs as half, padded with -64
__device__ int          g_npos;
__device__ float        g_partial[GRID];
__device__ unsigned int g_arrive = 0;

// ---------------------------------------------------------------------------
// K1: deterministic one-pass global compaction (no atomics, no global scan).
// ---------------------------------------------------------------------------
__global__ __launch_bounds__(K1TPB)
void compact_kernel(const int* __restrict__ yt, const float* __restrict__ yp) {
    __shared__ int s_warp[8];
    __shared__ int s_wscan[4];
    __shared__ int s_prefix;

    const int tid  = threadIdx.x;
    const int lane = tid & 31;
    const int w    = tid >> 5;
    const int cs   = blockIdx.x * CHUNK;

    // prefix count over [0, cs)
    int cnt = 0;
    const int4* yt4 = (const int4*)yt;
    for (int i = tid; i < (cs >> 2); i += K1TPB) {
        const int4 t = yt4[i];
        cnt += (t.x == 1) + (t.y == 1) + (t.z == 1) + (t.w == 1);
    }
    #pragma unroll
    for (int o = 16; o > 0; o >>= 1)
        cnt += __shfl_down_sync(0xffffffffu, cnt, o);
    if (lane == 0) s_warp[w] = cnt;

    // own chunk: threads 0..127 hold one element each
    int   lab = 0;
    float val = 0.f;
    if (tid < CHUNK) { lab = yt[cs + tid]; val = yp[cs + tid]; }
    const int flag = (lab == 1);
    const unsigned bal = __ballot_sync(0xffffffffu, flag);
    const int excl = __popc(bal & ((1u << lane) - 1u));
    if (lane == 0 && w < 4) s_wscan[w] = __popc(bal);
    __syncthreads();

    if (tid == 0) {
        int s = 0;
        #pragma unroll
        for (int i = 0; i < 8; i++) s += s_warp[i];
        s_prefix = s;
    }
    __syncthreads();

    const int P = s_prefix;                   // pos before this chunk
    if (tid < CHUNK) {
        int wbase = 0;
        #pragma unroll
        for (int i = 0; i < 4; i++) if (i < w) wbase += s_wscan[i];
        const int lpos = wbase + excl;        // pos rank within chunk
        if (flag) g_posc[P + lpos] = 1.0f - val;
        else      g_negh[(cs - P) + (tid - lpos)] = __float2half(val);
    }

    // last block: pads (disjoint from all scatter targets) + publish npos
    if (blockIdx.x == NCHK - 1) {
        __syncthreads();
        int cpos = 0;
        #pragma unroll
        for (int i = 0; i < 4; i++) cpos += s_wscan[i];
        const int npos = P + cpos;
        const int nneg = N_TOTAL - npos;
        int pos_end = (npos + ROWS - 1) & ~(ROWS - 1);
        if (pos_end < POS_HOT) pos_end = POS_HOT;
        for (int i = npos + tid; i < pos_end; i += K1TPB) g_posc[i] = -PADV;
        for (int j = nneg + tid; j < NEG_HOT; j += K1TPB)
            g_negh[j] = __float2half(-PADV);
        if (tid == 0) g_npos = npos;
    }
}

// ---------------------------------------------------------------------------
// K2 hot loop, templated on neg-slice count (4 when nneg<=8192, else 5).
// c-values come from smem (LDS.128); negs live in registers.
// ---------------------------------------------------------------------------
template <int KN>
__device__ __forceinline__ void hot_loop(const float4* __restrict__ sc4,
                                         const __half2* __restrict__ nr2,
                                         __half2* __restrict__ acc2,
                                         const int bx) {
    const __half2 one2 = __float2half2_rn(1.0f);
    #pragma unroll
    for (int g = 0; g < GMAX; g++) {
        const int r04 = (bx + g * GRID) * (ROWS / 4);
        const float4 ca = sc4[r04];
        const float4 cb = sc4[r04 + 1];
        __half2 c2[ROWS];
        c2[0] = __float2half2_rn(ca.x);  c2[1] = __float2half2_rn(ca.y);
        c2[2] = __float2half2_rn(ca.z);  c2[3] = __float2half2_rn(ca.w);
        c2[4] = __float2half2_rn(cb.x);  c2[5] = __float2half2_rn(cb.y);
        c2[6] = __float2half2_rn(cb.z);  c2[7] = __float2half2_rn(cb.w);

        #pragma unroll
        for (int k = 0; k < KN; k++) {
            const __half2 n2 = nr2[k];
            #pragma unroll
            for (int r = 0; r < ROWS; r++)
                acc2[r] = __hadd2(acc2[r], __hfma2_relu(n2, one2, c2[r]));
        }
    }
}

// ---------------------------------------------------------------------------
// K2: main hinge kernel. smem-staged c, register negs, branchless core.
// ---------------------------------------------------------------------------
__global__ __launch_bounds__(TPB, 1)
void main_kernel(float* __restrict__ out) {
    extern __shared__ float s_c[];          // POS_HOT floats (c-values + pads)
    __shared__ float s_red[32];
    __shared__ int   s_amlast;

    const int tid  = threadIdx.x;
    const int lane = tid & 31;
    const int warp = tid >> 5;

    // cooperative smem stage of the hot c region (coalesced float4)
    {
        const float4* gp4 = (const float4*)g_posc;
        float4*       sc4 = (float4*)s_c;
        #pragma unroll
        for (int i = tid; i < POS_HOT / 4; i += TPB)
            sc4[i] = gp4[i];
    }

    // hoist this thread's 10 negs (pre-converted halves) — overlaps the stage
    const __half2* negh2 = (const __half2*)g_negh;
    __half2 nr2[K2N];
    #pragma unroll
    for (int k = 0; k < K2N; k++)
        nr2[k] = negh2[k * TPB + tid];

    const int npos = g_npos;
    const int nneg = N_TOTAL - npos;
    __syncthreads();

    const __half2 z2 = __float2half2_rn(0.0f);
    __half2 acc2[ROWS];
    #pragma unroll
    for (int r = 0; r < ROWS; r++) acc2[r] = z2;

    // hot loop: slices 4 only when real negs extend past 8192
    const float4* sc4 = (const float4*)s_c;
    if (nneg > NEG_BASE) hot_loop<5>(sc4, nr2, acc2, blockIdx.x);
    else                 hot_loop<4>(sc4, nr2, acc2, blockIdx.x);

    const int npos_pad8 = (npos + ROWS - 1) & ~(ROWS - 1);
    float accv = 0.f;

    // cold fallback A: rows beyond POS_HOT (npos > 8288; never in practice)
    if (npos_pad8 > POS_HOT) {
        const __half2 one2 = __float2half2_rn(1.0f);
        for (int r0 = (blockIdx.x + GMAX * GRID) * ROWS; r0 < npos_pad8;
             r0 += GRID * ROWS) {
            __half2 c2[ROWS];
            #pragma unroll
            for (int r = 0; r < ROWS; r++)
                c2[r] = __float2half2_rn(g_posc[r0 + r]);
            #pragma unroll
            for (int k = 0; k < K2N; k++) {
                const __half2 n2 = nr2[k];
                #pragma unroll
                for (int r = 0; r < ROWS; r++)
                    acc2[r] = __hadd2(acc2[r], __hfma2_relu(n2, one2, c2[r]));
            }
        }
    }

    // cold fallback B: negs beyond NEG_HOT (> 15 sigma; never in practice)
    if (nneg > NEG_HOT) {
        for (int r0 = blockIdx.x * ROWS; r0 < npos_pad8; r0 += GRID * ROWS) {
            float ch[ROWS];
            #pragma unroll
            for (int r = 0; r < ROWS; r++) ch[r] = g_posc[r0 + r];
            for (int j = NEG_HOT + tid; j < nneg; j += TPB) {
                const float nk = __half2float(g_negh[j]);
                #pragma unroll
                for (int r = 0; r < ROWS; r++)
                    accv += fmaxf(ch[r] + nk, 0.0f);
            }
        }
    }

    // flush fp16 accumulators
    #pragma unroll
    for (int r = 0; r < ROWS; r++)
        accv += __low2float(acc2[r]) + __high2float(acc2[r]);

    // block reduction (fixed order)
    #pragma unroll
    for (int o = 16; o > 0; o >>= 1)
        accv += __shfl_down_sync(0xffffffffu, accv, o);
    if (lane == 0) s_red[warp] = accv;
    __syncthreads();
    if (warp == 0) {
        float v = s_red[lane];
        #pragma unroll
        for (int o = 16; o > 0; o >>= 1)
            v += __shfl_down_sync(0xffffffffu, v, o);
        if (lane == 0) g_partial[blockIdx.x] = v;
    }

    // last block finalizes (double, fixed order)
    if (tid == 0) {
        __threadfence();
        unsigned int prev = atomicAdd(&g_arrive, 1u);
        s_amlast = (prev == GRID - 1);
    }
    __syncthreads();
    if (!s_amlast) return;
    __threadfence();

    if (warp == 0) {
        double S = 0.0;
        for (int i = lane; i < GRID; i += 32) S += (double)g_partial[i];
        #pragma unroll
        for (int o = 16; o > 0; o >>= 1)
            S += __shfl_down_sync(0xffffffffu, S, o);
        if (lane == 0) {
            out[0] = (float)(S / ((double)npos * (double)nneg));
            g_arrive = 0u;    // reset for next graph replay
        }
    }
}

extern "C" void kernel_launch(void* const* d_in, const int* in_sizes, int n_in,
                              void* d_out, int out_size) {
    const int*   yt = (const int*)d_in[0];
    const float* yp = (const float*)d_in[1];

    const int smem_bytes = POS_HOT * sizeof(float);   // 33.2 KB
    compact_kernel<<<NCHK, K1TPB>>>(yt, yp);
    main_kernel<<<GRID, TPB, smem_bytes>>>((float*)d_out);
}